// round 9
// baseline (speedup 1.0000x reference)
#include <cuda_runtime.h>
#include <cstdint>

#define BATCH 256
#define CH    2048
#define HW    196
#define NEXP  16
#define NA    3000
#define KDIM  2048

#define MT       32          // batches per expert tile (N)
#define MAXTILES 24          // worst-case: 16 nonempty + floor(240/32) = 23
#define AB       64          // a-rows per CTA (M)
#define NABLK    47          // ceil(3000/64)
#define KC       32          // k-chunk (floats)
#define NCH      (KDIM/KC)   // 64 chunks
#define AP       36          // A smem pitch (floats)
#define BPF2     36          // B pitch in float2 per (sl,tig) row
#define BROW     (2*BPF2)    // 72 floats
#define BCHUNK   (16*BROW)   // 1152 floats per chunk per (hi|lo)
#define GGRID    888         // 148 SMs x 6 CTAs

// smem float offsets
#define SM_A   0                 // [2][64][36]  = 4608
#define SM_BH  4608              // [2][1152]    = 2304
#define SM_BL  6912              // [2][1152]    = 2304
#define SM_TOT 9216              // floats -> 36864 B

__device__ float g_attended[BATCH * CH];
__device__ int   g_perm[BATCH];
__device__ int   g_tile_e[MAXTILES];
__device__ int   g_tile_m0[MAXTILES];
__device__ int   g_tile_cnt[MAXTILES];
__device__ int   g_numtiles;
// staged B panels: [tile][chunk][(sl*4+tig)*72 + 2n + h]
__device__ __align__(16) float g_stage_hi[MAXTILES][NCH][BCHUNK];
__device__ __align__(16) float g_stage_lo[MAXTILES][NCH][BCHUNK];

// ---------------- helpers ----------------
__device__ __forceinline__ uint32_t to_tf32(float x) {
    uint32_t r;
    asm("cvt.rna.tf32.f32 %0, %1;" : "=r"(r) : "f"(x));
    return r;
}
__device__ __forceinline__ void mma8(float c[4], const uint32_t a[4],
                                     uint32_t b0, uint32_t b1) {
    asm volatile(
        "mma.sync.aligned.m16n8k8.row.col.f32.tf32.tf32.f32 "
        "{%0,%1,%2,%3}, {%4,%5,%6,%7}, {%8,%9}, {%0,%1,%2,%3};"
        : "+f"(c[0]), "+f"(c[1]), "+f"(c[2]), "+f"(c[3])
        : "r"(a[0]), "r"(a[1]), "r"(a[2]), "r"(a[3]), "r"(b0), "r"(b1));
}
__device__ __forceinline__ void cp16(uint32_t sdst, const void* g) {
    asm volatile("cp.async.cg.shared.global [%0], [%1], 16;" :: "r"(sdst), "l"(g));
}
__device__ __forceinline__ void cp_commit() {
    asm volatile("cp.async.commit_group;" ::: "memory");
}
__device__ __forceinline__ void cp_wait1() {
    asm volatile("cp.async.wait_group 1;" ::: "memory");
}

// ---------------------------------------------------------------------------
// Kernel 1: masked weighted average pool (DRAM-bound, at floor).
// ---------------------------------------------------------------------------
__global__ void pool_kernel(const float* __restrict__ mask,
                            const float* __restrict__ feat) {
    int b   = blockIdx.x;
    int tid = threadIdx.x;
    int wid = tid >> 5, lane = tid & 31;

    __shared__ __align__(16) float m_s[HW];
    __shared__ float warp_sum[8];
    __shared__ float s_inv;

    float v = 0.f;
    if (tid < HW) {
        v = mask[b * HW + tid] + 1e-10f;
        m_s[tid] = v;
    }
    #pragma unroll
    for (int o = 16; o > 0; o >>= 1) v += __shfl_down_sync(0xffffffffu, v, o);
    if (lane == 0) warp_sum[wid] = v;
    __syncthreads();
    if (tid == 0) {
        float s = 0.f;
        #pragma unroll
        for (int i = 0; i < 8; i++) s += warp_sum[i];
        s_inv = 1.0f / s;
    }
    __syncthreads();
    float inv = s_inv;

    const float4* m4 = (const float4*)m_s;
    float4 mA = m4[lane];
    float4 mB = (lane < 17) ? m4[lane + 32] : make_float4(0.f, 0.f, 0.f, 0.f);

    int cbase = blockIdx.y * 256 + wid * 32;
    for (int it = 0; it < 32; it++) {
        int c = cbase + it;
        const float4* row = (const float4*)(feat + ((size_t)b * CH + c) * HW);
        float4 f = row[lane];
        float s = f.x * mA.x + f.y * mA.y + f.z * mA.z + f.w * mA.w;
        if (lane < 17) {
            float4 f2 = row[lane + 32];
            s += f2.x * mB.x + f2.y * mB.y + f2.z * mB.z + f2.w * mB.w;
        }
        #pragma unroll
        for (int o = 16; o > 0; o >>= 1) s += __shfl_down_sync(0xffffffffu, s, o);
        if (lane == 0) g_attended[b * CH + c] = s * inv;
    }
}

// ---------------------------------------------------------------------------
// Kernel 2: group batches by expert (stable), tiles of <=32.
// ---------------------------------------------------------------------------
__global__ void group_kernel(const void* __restrict__ inst) {
    int tid = threadIdx.x;
    __shared__ int odd_nz;
    __shared__ int sh_e[BATCH];
    __shared__ int cnt[NEXP];
    __shared__ int off[NEXP + 1];

    if (tid == 0) odd_nz = 0;
    __syncthreads();
    const int* iv = (const int*)inst;
    if (tid < BATCH / 2 && iv[2 * tid + 1] != 0) atomicExch(&odd_nz, 1);
    __syncthreads();

    int e;
    if (odd_nz == 0) e = (int)((const long long*)inst)[tid];
    else             e = iv[tid];

    sh_e[tid] = e;
    if (tid < NEXP) cnt[tid] = 0;
    __syncthreads();

    atomicAdd(&cnt[e], 1);
    int rank = 0;
    for (int j = 0; j < tid; j++) rank += (sh_e[j] == e);
    __syncthreads();

    if (tid == 0) {
        off[0] = 0;
        for (int i = 0; i < NEXP; i++) off[i + 1] = off[i] + cnt[i];
        int nt = 0;
        for (int ei = 0; ei < NEXP; ei++)
            for (int s = 0; s < cnt[ei]; s += MT) {
                g_tile_e[nt]   = ei;
                g_tile_m0[nt]  = off[ei] + s;
                g_tile_cnt[nt] = min(MT, cnt[ei] - s);
                nt++;
            }
        g_numtiles = nt;
    }
    __syncthreads();
    g_perm[off[e] + rank] = tid;
}

// ---------------------------------------------------------------------------
// Kernel 3: stage k-pair-packed tf32 hi/lo B panels.
//   [tile][c][(sl*4+tig)*72 + 2n + h] = tf32_part(att[bb[n]][k]),
//   k = c*32 + sl*8 + tig + 4h.  grid (16, MAXTILES) x 128 thr (4 chunks/blk).
// ---------------------------------------------------------------------------
__global__ void stage_kernel() {
    int tile = blockIdx.y;
    if (tile >= g_numtiles) return;
    int k0 = blockIdx.x * 128;
    int tid = threadIdx.x;

    __shared__ float s[MT][132];
    __shared__ int s_bb[MT];
    if (tid < MT) {
        int m0 = g_tile_m0[tile], mcnt = g_tile_cnt[tile];
        s_bb[tid] = g_perm[m0 + min(tid, mcnt - 1)];
    }
    __syncthreads();

    // load 32 rows x 128 floats = 1024 f4, 8 per thread
    #pragma unroll
    for (int i = 0; i < 8; i++) {
        int f4 = tid + 128 * i;
        int r = f4 >> 5, c = f4 & 31;
        float4 v = *(const float4*)(g_attended + (size_t)s_bb[r] * KDIM + k0 + c * 4);
        *(float4*)&s[r][c * 4] = v;
    }
    __syncthreads();

    int p = tid & 63, half = tid >> 6;
    int cc = p >> 4, sl = (p >> 2) & 3, tig = p & 3;
    int kl = cc * 32 + sl * 8 + tig;
    int c  = blockIdx.x * 4 + cc;
    float* dh = &g_stage_hi[tile][c][(sl * 4 + tig) * BROW];
    float* dl = &g_stage_lo[tile][c][(sl * 4 + tig) * BROW];

    #pragma unroll
    for (int i = 0; i < 16; i++) {
        int n = half * 16 + i;
        float x0 = s[n][kl], x1 = s[n][kl + 4];
        float h0 = __uint_as_float(to_tf32(x0));
        float h1 = __uint_as_float(to_tf32(x1));
        float l0 = __uint_as_float(to_tf32(x0 - h0));
        float l1 = __uint_as_float(to_tf32(x1 - h1));
        *(float2*)(dh + 2 * n) = make_float2(h0, h1);
        *(float2*)(dl + 2 * n) = make_float2(l0, l1);
    }
}

// ---------------------------------------------------------------------------
// Kernel 4: persistent grouped GEMM via mma.sync tf32 (3xTF32).
// Flattened item loop over (tile, ablock); grid = 888 (6 CTAs/SM exactly).
// CTA: 128 thr / 4 warps; warp = 16 a-rows x (nf*8) batches, nf<=4 skipped.
// ---------------------------------------------------------------------------
__global__ __launch_bounds__(128, 6)
void gemm_kernel(const float* __restrict__ W,
                 const float* __restrict__ bias,
                 float* __restrict__ out) {
    extern __shared__ __align__(16) float dsm[];
    uint32_t sm_u = (uint32_t)__cvta_generic_to_shared(dsm);

    int tid  = threadIdx.x;
    int w    = tid >> 5, lane = tid & 31;
    int g    = lane >> 2, tig = lane & 3;
    int r0 = tid >> 3, c4 = tid & 7;
    uint32_t adst0 = sm_u + (SM_A + r0 * AP + c4 * 4) * 4;

    __shared__ int s_bb[MT];

    int numtiles = g_numtiles;
    int total = numtiles * NABLK;

    for (int item = blockIdx.x; item < total; item += GGRID) {
        int tile = item % numtiles;
        int ab   = item / numtiles;
        int e    = g_tile_e[tile];
        int mcnt = g_tile_cnt[tile];
        int nf   = (mcnt + 7) >> 3;
        int a0   = ab * AB;

        __syncthreads();   // previous item's epilogue done before s_bb rewrite
        if (tid < MT) s_bb[tid] = g_perm[g_tile_m0[tile] + min(tid, mcnt - 1)];
        __syncthreads();

        const char* Wexp = (const char*)(W + (size_t)e * NA * KDIM);
        uint32_t a_off[4];
        #pragma unroll
        for (int j = 0; j < 4; j++)
            a_off[j] = (uint32_t)min(a0 + r0 + 16 * j, NA - 1) * (KDIM * 4) + c4 * 16;
        const char* bsrcH = (const char*)&g_stage_hi[tile][0][0];
        const char* bsrcL = (const char*)&g_stage_lo[tile][0][0];

        auto issue = [&](int c) {
            int buf = c & 1;
            const char* wsrc = Wexp + (size_t)c * (KC * 4);
            uint32_t ad = adst0 + buf * (AB * AP * 4);
            #pragma unroll
            for (int j = 0; j < 4; j++)
                cp16(ad + j * (16 * AP * 4), wsrc + a_off[j]);
            const char* bh = bsrcH + (size_t)c * (BCHUNK * 4);
            const char* bl = bsrcL + (size_t)c * (BCHUNK * 4);
            uint32_t dh = sm_u + (SM_BH + buf * BCHUNK) * 4;
            uint32_t dl = sm_u + (SM_BL + buf * BCHUNK) * 4;
            cp16(dh + tid * 16, bh + tid * 16);
            cp16(dh + (tid + 128) * 16, bh + (tid + 128) * 16);
            cp16(dl + tid * 16, bl + tid * 16);
            cp16(dl + (tid + 128) * 16, bl + (tid + 128) * 16);
            if (tid < 32) {
                cp16(dh + (tid + 256) * 16, bh + (tid + 256) * 16);
                cp16(dl + (tid + 256) * 16, bl + (tid + 256) * 16);
            }
        };

        issue(0); cp_commit();
        issue(1); cp_commit();

        float acc[4][4];
        #pragma unroll
        for (int f = 0; f < 4; f++)
            #pragma unroll
            for (int q = 0; q < 4; q++) acc[f][q] = 0.f;

        for (int c = 0; c < NCH; c++) {
            cp_wait1();
            __syncthreads();
            int buf = c & 1;
            const float* As = dsm + SM_A + buf * (AB * AP) + w * 16 * AP;
            const float* Bh = dsm + SM_BH + buf * BCHUNK;
            const float* Bl = dsm + SM_BL + buf * BCHUNK;

            #pragma unroll
            for (int sl = 0; sl < KC / 8; sl++) {
                int kk = sl * 8;
                float a0f = As[g * AP + kk + tig];
                float a1f = As[(g + 8) * AP + kk + tig];
                float a2f = As[g * AP + kk + tig + 4];
                float a3f = As[(g + 8) * AP + kk + tig + 4];
                uint32_t ahi[4], alo[4];
                ahi[0] = to_tf32(a0f); alo[0] = to_tf32(a0f - __uint_as_float(ahi[0]));
                ahi[1] = to_tf32(a1f); alo[1] = to_tf32(a1f - __uint_as_float(ahi[1]));
                ahi[2] = to_tf32(a2f); alo[2] = to_tf32(a2f - __uint_as_float(ahi[2]));
                ahi[3] = to_tf32(a3f); alo[3] = to_tf32(a3f - __uint_as_float(ahi[3]));

                int bbase = (sl * 4 + tig) * BROW + 2 * g;
                float2 bh2[4], bl2[4];
                #pragma unroll
                for (int f = 0; f < 4; f++)
                    if (f < nf) {
                        bh2[f] = *(const float2*)(Bh + bbase + 16 * f);
                        bl2[f] = *(const float2*)(Bl + bbase + 16 * f);
                    }
                #pragma unroll
                for (int f = 0; f < 4; f++)
                    if (f < nf)
                        mma8(acc[f], ahi, __float_as_uint(bh2[f].x),
                                          __float_as_uint(bh2[f].y));
                #pragma unroll
                for (int f = 0; f < 4; f++)
                    if (f < nf)
                        mma8(acc[f], ahi, __float_as_uint(bl2[f].x),
                                          __float_as_uint(bl2[f].y));
                #pragma unroll
                for (int f = 0; f < 4; f++)
                    if (f < nf)
                        mma8(acc[f], alo, __float_as_uint(bh2[f].x),
                                          __float_as_uint(bh2[f].y));
            }
            __syncthreads();
            if (c + 2 < NCH) issue(c + 2);
            cp_commit();
        }

        // ---- epilogue ----
        int ra = a0 + w * 16 + g;
        int rb = ra + 8;
        float bv0 = (ra < NA) ? bias[e * NA + ra] : 0.f;
        float bv1 = (rb < NA) ? bias[e * NA + rb] : 0.f;
        #pragma unroll
        for (int f = 0; f < 4; f++) {
            int n0 = 8 * f + 2 * tig, n1 = n0 + 1;
            if (n0 < mcnt) {
                if (ra < NA) out[(size_t)s_bb[n0] * NA + ra] = acc[f][0] + bv0;
                if (rb < NA) out[(size_t)s_bb[n0] * NA + rb] = acc[f][2] + bv1;
            }
            if (n1 < mcnt) {
                if (ra < NA) out[(size_t)s_bb[n1] * NA + ra] = acc[f][1] + bv0;
                if (rb < NA) out[(size_t)s_bb[n1] * NA + rb] = acc[f][3] + bv1;
            }
        }
    }
}

// ---------------------------------------------------------------------------
extern "C" void kernel_launch(void* const* d_in, const int* in_sizes, int n_in,
                              void* d_out, int out_size) {
    const float* mask = (const float*)d_in[0];
    const float* feat = (const float*)d_in[1];
    const float* W    = (const float*)d_in[2];
    const float* bias = (const float*)d_in[3];
    const void*  inst = d_in[4];
    float* out = (float*)d_out;

    const int GEMM_SMEM = SM_TOT * 4;   // 36864 B
    cudaFuncSetAttribute(gemm_kernel,
                         cudaFuncAttributeMaxDynamicSharedMemorySize, GEMM_SMEM);

    pool_kernel<<<dim3(BATCH, 8), 256>>>(mask, feat);
    group_kernel<<<1, BATCH>>>(inst);
    stage_kernel<<<dim3(KDIM / 128, MAXTILES), 128>>>();
    gemm_kernel<<<GGRID, 128, GEMM_SMEM>>>(W, bias, out);
}

// round 10
// speedup vs baseline: 1.0991x; 1.0991x over previous
#include <cuda_runtime.h>
#include <cstdint>

#define BATCH 256
#define CH    2048
#define HW    196
#define NEXP  16
#define NA    3000
#define KDIM  2048

#define MT       24          // batches per expert tile (N)
#define MAXTILES 32
#define AB       64          // a-rows per item (M)
#define NABLK    47          // ceil(3000/64)
#define KC       32          // k-chunk (floats)
#define NCH      (KDIM/KC)   // 64 chunks total
#define NCH2     (NCH/2)     // 32 chunks per K-half item
#define AP       36          // A smem pitch (floats)
#define BPF2     28          // B pitch in float2 per (sl,tig) row
#define BROW     (2*BPF2)    // 56 floats
#define BCHUNK   (16*BROW)   // 896 floats per chunk per (hi|lo)
#define GGRID    888         // 148 SMs x 6 CTAs

// smem float offsets
#define SM_A   0                 // [2][64][36]  = 4608
#define SM_BH  4608              // [2][896]     = 1792
#define SM_BL  6400              // [2][896]     = 1792
#define SM_TOT 8192              // floats -> 32768 B

__device__ float g_attended[BATCH * CH];
__device__ int   g_perm[BATCH];
__device__ int   g_expert[BATCH];
__device__ int   g_tile_e[MAXTILES];
__device__ int   g_tile_m0[MAXTILES];
__device__ int   g_tile_cnt[MAXTILES];
__device__ int   g_numtiles;
__device__ int   g_ctr;
__device__ float g_partial[2][BATCH * NA];                       // 6.1 MB
__device__ __align__(16) float g_stage_hi[MAXTILES][NCH][BCHUNK];
__device__ __align__(16) float g_stage_lo[MAXTILES][NCH][BCHUNK];

// ---------------- helpers ----------------
__device__ __forceinline__ uint32_t to_tf32(float x) {
    uint32_t r;
    asm("cvt.rna.tf32.f32 %0, %1;" : "=r"(r) : "f"(x));
    return r;
}
__device__ __forceinline__ void mma8(float c[4], const uint32_t a[4],
                                     uint32_t b0, uint32_t b1) {
    asm volatile(
        "mma.sync.aligned.m16n8k8.row.col.f32.tf32.tf32.f32 "
        "{%0,%1,%2,%3}, {%4,%5,%6,%7}, {%8,%9}, {%0,%1,%2,%3};"
        : "+f"(c[0]), "+f"(c[1]), "+f"(c[2]), "+f"(c[3])
        : "r"(a[0]), "r"(a[1]), "r"(a[2]), "r"(a[3]), "r"(b0), "r"(b1));
}
__device__ __forceinline__ void cp16(uint32_t sdst, const void* g) {
    asm volatile("cp.async.cg.shared.global [%0], [%1], 16;" :: "r"(sdst), "l"(g));
}
__device__ __forceinline__ void cp_commit() {
    asm volatile("cp.async.commit_group;" ::: "memory");
}
__device__ __forceinline__ void cp_wait1() {
    asm volatile("cp.async.wait_group 1;" ::: "memory");
}

// ---------------------------------------------------------------------------
// Kernel 1: masked weighted average pool (DRAM-bound, at floor).
// ---------------------------------------------------------------------------
__global__ void pool_kernel(const float* __restrict__ mask,
                            const float* __restrict__ feat) {
    int b   = blockIdx.x;
    int tid = threadIdx.x;
    int wid = tid >> 5, lane = tid & 31;

    __shared__ __align__(16) float m_s[HW];
    __shared__ float warp_sum[8];
    __shared__ float s_inv;

    float v = 0.f;
    if (tid < HW) {
        v = mask[b * HW + tid] + 1e-10f;
        m_s[tid] = v;
    }
    #pragma unroll
    for (int o = 16; o > 0; o >>= 1) v += __shfl_down_sync(0xffffffffu, v, o);
    if (lane == 0) warp_sum[wid] = v;
    __syncthreads();
    if (tid == 0) {
        float s = 0.f;
        #pragma unroll
        for (int i = 0; i < 8; i++) s += warp_sum[i];
        s_inv = 1.0f / s;
    }
    __syncthreads();
    float inv = s_inv;

    const float4* m4 = (const float4*)m_s;
    float4 mA = m4[lane];
    float4 mB = (lane < 17) ? m4[lane + 32] : make_float4(0.f, 0.f, 0.f, 0.f);

    int cbase = blockIdx.y * 256 + wid * 32;
    for (int it = 0; it < 32; it++) {
        int c = cbase + it;
        const float4* row = (const float4*)(feat + ((size_t)b * CH + c) * HW);
        float4 f = row[lane];
        float s = f.x * mA.x + f.y * mA.y + f.z * mA.z + f.w * mA.w;
        if (lane < 17) {
            float4 f2 = row[lane + 32];
            s += f2.x * mB.x + f2.y * mB.y + f2.z * mB.z + f2.w * mB.w;
        }
        #pragma unroll
        for (int o = 16; o > 0; o >>= 1) s += __shfl_down_sync(0xffffffffu, s, o);
        if (lane == 0) g_attended[b * CH + c] = s * inv;
    }
}

// ---------------------------------------------------------------------------
// Kernel 2: group batches by expert (stable), tiles of <=24, reset counter.
// ---------------------------------------------------------------------------
__global__ void group_kernel(const void* __restrict__ inst) {
    int tid = threadIdx.x;
    __shared__ int odd_nz;
    __shared__ int sh_e[BATCH];
    __shared__ int cnt[NEXP];
    __shared__ int off[NEXP + 1];

    if (tid == 0) { odd_nz = 0; g_ctr = 0; }
    __syncthreads();
    const int* iv = (const int*)inst;
    if (tid < BATCH / 2 && iv[2 * tid + 1] != 0) atomicExch(&odd_nz, 1);
    __syncthreads();

    int e;
    if (odd_nz == 0) e = (int)((const long long*)inst)[tid];
    else             e = iv[tid];

    sh_e[tid] = e;
    g_expert[tid] = e;
    if (tid < NEXP) cnt[tid] = 0;
    __syncthreads();

    atomicAdd(&cnt[e], 1);
    int rank = 0;
    for (int j = 0; j < tid; j++) rank += (sh_e[j] == e);
    __syncthreads();

    if (tid == 0) {
        off[0] = 0;
        for (int i = 0; i < NEXP; i++) off[i + 1] = off[i] + cnt[i];
        int nt = 0;
        for (int ei = 0; ei < NEXP; ei++)
            for (int s = 0; s < cnt[ei]; s += MT) {
                g_tile_e[nt]   = ei;
                g_tile_m0[nt]  = off[ei] + s;
                g_tile_cnt[nt] = min(MT, cnt[ei] - s);
                nt++;
            }
        g_numtiles = nt;
    }
    __syncthreads();
    g_perm[off[e] + rank] = tid;
}

// ---------------------------------------------------------------------------
// Kernel 3: stage k-pair-packed tf32 hi/lo B panels.
//   [tile][c][(sl*4+tig)*56 + 2n + h] = tf32_part(att[bb[n]][k]),
//   k = c*32 + sl*8 + tig + 4h.  grid (16, MAXTILES) x 128 thr.
// ---------------------------------------------------------------------------
__global__ void stage_kernel() {
    int tile = blockIdx.y;
    if (tile >= g_numtiles) return;
    int k0 = blockIdx.x * 128;
    int tid = threadIdx.x;

    __shared__ float s[MT][128 + 4];
    __shared__ int s_bb[MT];
    if (tid < MT) {
        int m0 = g_tile_m0[tile], mcnt = g_tile_cnt[tile];
        s_bb[tid] = g_perm[m0 + min(tid, mcnt - 1)];
    }
    __syncthreads();

    #pragma unroll
    for (int i = 0; i < 6; i++) {
        int f4 = tid + 128 * i;
        int r = f4 >> 5, c = f4 & 31;
        float4 v = *(const float4*)(g_attended + (size_t)s_bb[r] * KDIM + k0 + c * 4);
        *(float4*)&s[r][c * 4] = v;
    }
    __syncthreads();

    int p = tid & 63, half = tid >> 6;
    int cc = p >> 4, sl = (p >> 2) & 3, tig = p & 3;
    int kl = cc * 32 + sl * 8 + tig;
    int c  = blockIdx.x * 4 + cc;
    float* dh = &g_stage_hi[tile][c][(sl * 4 + tig) * BROW];
    float* dl = &g_stage_lo[tile][c][(sl * 4 + tig) * BROW];

    #pragma unroll
    for (int i = 0; i < 12; i++) {
        int n = half * 12 + i;
        float x0 = s[n][kl], x1 = s[n][kl + 4];
        float h0 = __uint_as_float(to_tf32(x0));
        float h1 = __uint_as_float(to_tf32(x1));
        float l0 = __uint_as_float(to_tf32(x0 - h0));
        float l1 = __uint_as_float(to_tf32(x1 - h1));
        *(float2*)(dh + 2 * n) = make_float2(h0, h1);
        *(float2*)(dl + 2 * n) = make_float2(l0, l1);
    }
}

// ---------------------------------------------------------------------------
// Kernel 4: persistent work-stealing grouped GEMM, mma.sync tf32 (3xTF32).
// Item = (tile, ablock, khalf): 32 k-chunks -> ~1692 items over 888 CTAs.
// K-halves write disjoint g_partial buffers (deterministic); reduce adds.
// ---------------------------------------------------------------------------
__global__ __launch_bounds__(128, 6)
void gemm_kernel(const float* __restrict__ W) {
    extern __shared__ __align__(16) float dsm[];
    uint32_t sm_u = (uint32_t)__cvta_generic_to_shared(dsm);

    int tid  = threadIdx.x;
    int w    = tid >> 5, lane = tid & 31;
    int g    = lane >> 2, tig = lane & 3;
    int r0 = tid >> 3, c4 = tid & 7;
    uint32_t adst0 = sm_u + (SM_A + r0 * AP + c4 * 4) * 4;

    __shared__ int s_bb[MT];
    __shared__ int s_item;

    int numtiles = g_numtiles;
    int total = numtiles * NABLK * 2;

    for (;;) {
        if (tid == 0) s_item = atomicAdd(&g_ctr, 1);
        __syncthreads();            // also: prior epilogue done before s_bb rewrite
        int it = s_item;
        if (it >= total) break;

        int khalf = it & 1;
        int r     = it >> 1;
        int tile  = r % numtiles;
        int ab    = r / numtiles;
        int e     = g_tile_e[tile];
        int mcnt  = g_tile_cnt[tile];
        int nf    = (mcnt + 7) >> 3;
        int a0    = ab * AB;

        if (tid < MT) s_bb[tid] = g_perm[g_tile_m0[tile] + min(tid, mcnt - 1)];
        __syncthreads();

        const char* Wexp = (const char*)(W + (size_t)e * NA * KDIM)
                         + (size_t)khalf * (NCH2 * KC * 4);
        uint32_t a_off[4];
        #pragma unroll
        for (int j = 0; j < 4; j++)
            a_off[j] = (uint32_t)min(a0 + r0 + 16 * j, NA - 1) * (KDIM * 4) + c4 * 16;
        const char* bsrcH = (const char*)&g_stage_hi[tile][khalf * NCH2][0];
        const char* bsrcL = (const char*)&g_stage_lo[tile][khalf * NCH2][0];

        auto issue = [&](int c) {
            int buf = c & 1;
            const char* wsrc = Wexp + (size_t)c * (KC * 4);
            uint32_t ad = adst0 + buf * (AB * AP * 4);
            #pragma unroll
            for (int j = 0; j < 4; j++)
                cp16(ad + j * (16 * AP * 4), wsrc + a_off[j]);
            const char* bh = bsrcH + (size_t)c * (BCHUNK * 4);
            const char* bl = bsrcL + (size_t)c * (BCHUNK * 4);
            uint32_t dh = sm_u + (SM_BH + buf * BCHUNK) * 4;
            uint32_t dl = sm_u + (SM_BL + buf * BCHUNK) * 4;
            cp16(dh + tid * 16, bh + tid * 16);
            cp16(dl + tid * 16, bl + tid * 16);
            if (tid < 96) {
                cp16(dh + 2048 + tid * 16, bh + 2048 + tid * 16);
                cp16(dl + 2048 + tid * 16, bl + 2048 + tid * 16);
            }
        };

        issue(0); cp_commit();
        issue(1); cp_commit();

        float acc[3][4];
        #pragma unroll
        for (int f = 0; f < 3; f++)
            #pragma unroll
            for (int q = 0; q < 4; q++) acc[f][q] = 0.f;

        for (int c = 0; c < NCH2; c++) {
            cp_wait1();
            __syncthreads();
            int buf = c & 1;
            const float* As = dsm + SM_A + buf * (AB * AP) + w * 16 * AP;
            const float* Bh = dsm + SM_BH + buf * BCHUNK;
            const float* Bl = dsm + SM_BL + buf * BCHUNK;

            #pragma unroll
            for (int sl = 0; sl < KC / 8; sl++) {
                int kk = sl * 8;
                float a0f = As[g * AP + kk + tig];
                float a1f = As[(g + 8) * AP + kk + tig];
                float a2f = As[g * AP + kk + tig + 4];
                float a3f = As[(g + 8) * AP + kk + tig + 4];
                uint32_t ahi[4], alo[4];
                ahi[0] = to_tf32(a0f); alo[0] = to_tf32(a0f - __uint_as_float(ahi[0]));
                ahi[1] = to_tf32(a1f); alo[1] = to_tf32(a1f - __uint_as_float(ahi[1]));
                ahi[2] = to_tf32(a2f); alo[2] = to_tf32(a2f - __uint_as_float(ahi[2]));
                ahi[3] = to_tf32(a3f); alo[3] = to_tf32(a3f - __uint_as_float(ahi[3]));

                int bbase = (sl * 4 + tig) * BROW + 2 * g;
                float2 bh2[3], bl2[3];
                #pragma unroll
                for (int f = 0; f < 3; f++)
                    if (f < nf) {
                        bh2[f] = *(const float2*)(Bh + bbase + 16 * f);
                        bl2[f] = *(const float2*)(Bl + bbase + 16 * f);
                    }
                #pragma unroll
                for (int f = 0; f < 3; f++)
                    if (f < nf)
                        mma8(acc[f], ahi, __float_as_uint(bh2[f].x),
                                          __float_as_uint(bh2[f].y));
                #pragma unroll
                for (int f = 0; f < 3; f++)
                    if (f < nf)
                        mma8(acc[f], ahi, __float_as_uint(bl2[f].x),
                                          __float_as_uint(bl2[f].y));
                #pragma unroll
                for (int f = 0; f < 3; f++)
                    if (f < nf)
                        mma8(acc[f], alo, __float_as_uint(bh2[f].x),
                                          __float_as_uint(bh2[f].y));
            }
            __syncthreads();
            if (c + 2 < NCH2) issue(c + 2);
            cp_commit();
        }

        // ---- epilogue: write K-half partials (no bias here) ----
        float* po = &g_partial[khalf][0];
        int ra = a0 + w * 16 + g;
        int rb = ra + 8;
        #pragma unroll
        for (int f = 0; f < 3; f++) {
            int n0 = 8 * f + 2 * tig, n1 = n0 + 1;
            if (n0 < mcnt) {
                if (ra < NA) po[(size_t)s_bb[n0] * NA + ra] = acc[f][0];
                if (rb < NA) po[(size_t)s_bb[n0] * NA + rb] = acc[f][2];
            }
            if (n1 < mcnt) {
                if (ra < NA) po[(size_t)s_bb[n1] * NA + ra] = acc[f][1];
                if (rb < NA) po[(size_t)s_bb[n1] * NA + rb] = acc[f][3];
            }
        }
    }
}

// ---------------------------------------------------------------------------
// Kernel 5: out = partial[0] + partial[1] + bias[expert[b]]  (float4).
// grid 750 x 256: 192000 float4 = 256*3000 floats.
// ---------------------------------------------------------------------------
__global__ void reduce_kernel(const float* __restrict__ bias,
                              float* __restrict__ out) {
    int idx = blockIdx.x * 256 + threadIdx.x;       // 0..191999
    int b = idx / (NA / 4), q = idx % (NA / 4);
    int e = g_expert[b];
    float4 p0 = *(const float4*)(&g_partial[0][(size_t)b * NA + q * 4]);
    float4 p1 = *(const float4*)(&g_partial[1][(size_t)b * NA + q * 4]);
    float4 bv = *(const float4*)(bias + (size_t)e * NA + q * 4);
    float4 o;
    o.x = p0.x + p1.x + bv.x;
    o.y = p0.y + p1.y + bv.y;
    o.z = p0.z + p1.z + bv.z;
    o.w = p0.w + p1.w + bv.w;
    *(float4*)(out + (size_t)b * NA + q * 4) = o;
}

// ---------------------------------------------------------------------------
extern "C" void kernel_launch(void* const* d_in, const int* in_sizes, int n_in,
                              void* d_out, int out_size) {
    const float* mask = (const float*)d_in[0];
    const float* feat = (const float*)d_in[1];
    const float* W    = (const float*)d_in[2];
    const float* bias = (const float*)d_in[3];
    const void*  inst = d_in[4];
    float* out = (float*)d_out;

    const int GEMM_SMEM = SM_TOT * 4;   // 32768 B
    cudaFuncSetAttribute(gemm_kernel,
                         cudaFuncAttributeMaxDynamicSharedMemorySize, GEMM_SMEM);

    pool_kernel<<<dim3(BATCH, 8), 256>>>(mask, feat);
    group_kernel<<<1, BATCH>>>(inst);
    stage_kernel<<<dim3(KDIM / 128, MAXTILES), 128>>>();
    gemm_kernel<<<GGRID, 128, GEMM_SMEM>>>(W);
    reduce_kernel<<<750, 256>>>(bias, out);
}

// round 11
// speedup vs baseline: 1.1222x; 1.0210x over previous
#include <cuda_runtime.h>
#include <cstdint>

#define BATCH 256
#define CH    2048
#define HW    196
#define NEXP  16
#define NA    3000
#define KDIM  2048

#define MT       24          // batches per expert tile (N)
#define MAXTILES 32
#define AB       64          // a-rows per item (M)
#define NABLK    47          // ceil(3000/64)
#define KC       32          // k-chunk (floats)
#define NCH      (KDIM/KC)   // 64 chunks total
#define NKQ      4           // K split into quarters
#define NCHQ     (NCH/NKQ)   // 16 chunks per item
#define AP       36          // A smem pitch (floats)
#define BQROW    96          // packed B row: 24 n x 4 (h0,h1,l0,l1)
#define BQPITCH  104         // smem pitch (floats): 8*tig+4*g banks, conflict-free
#define GGRID    888         // 148 SMs x 6 CTAs

// smem float offsets
#define SM_A   0                 // [2][64][36]   = 4608
#define SM_B   4608              // [2][16][104]  = 3328
#define SM_TOT 7936              // floats -> 31744 B

__device__ float g_attended[BATCH * CH];
__device__ int   g_perm[BATCH];
__device__ int   g_expert[BATCH];
__device__ int   g_tile_e[MAXTILES];
__device__ int   g_tile_m0[MAXTILES];
__device__ int   g_tile_cnt[MAXTILES];
__device__ int   g_numtiles;
__device__ int   g_ctr;
__device__ float g_partial[NKQ][BATCH * NA];                     // 12.3 MB
// staged B: [tile][chunk][row16][96]: row=(sl*4+tig), per n a float4 quad
__device__ __align__(16) float g_stage[MAXTILES][NCH][16 * BQROW];

// ---------------- helpers ----------------
__device__ __forceinline__ void mma8(float c[4], const uint32_t a[4],
                                     uint32_t b0, uint32_t b1) {
    asm volatile(
        "mma.sync.aligned.m16n8k8.row.col.f32.tf32.tf32.f32 "
        "{%0,%1,%2,%3}, {%4,%5,%6,%7}, {%8,%9}, {%0,%1,%2,%3};"
        : "+f"(c[0]), "+f"(c[1]), "+f"(c[2]), "+f"(c[3])
        : "r"(a[0]), "r"(a[1]), "r"(a[2]), "r"(a[3]), "r"(b0), "r"(b1));
}
__device__ __forceinline__ void cp16(uint32_t sdst, const void* g) {
    asm volatile("cp.async.cg.shared.global [%0], [%1], 16;" :: "r"(sdst), "l"(g));
}
__device__ __forceinline__ void cp_commit() {
    asm volatile("cp.async.commit_group;" ::: "memory");
}
__device__ __forceinline__ void cp_wait1() {
    asm volatile("cp.async.wait_group 1;" ::: "memory");
}

// ---------------------------------------------------------------------------
// Kernel 1: masked weighted average pool (DRAM-bound, at floor).
// ---------------------------------------------------------------------------
__global__ void pool_kernel(const float* __restrict__ mask,
                            const float* __restrict__ feat) {
    int b   = blockIdx.x;
    int tid = threadIdx.x;
    int wid = tid >> 5, lane = tid & 31;

    __shared__ __align__(16) float m_s[HW];
    __shared__ float warp_sum[8];
    __shared__ float s_inv;

    float v = 0.f;
    if (tid < HW) {
        v = mask[b * HW + tid] + 1e-10f;
        m_s[tid] = v;
    }
    #pragma unroll
    for (int o = 16; o > 0; o >>= 1) v += __shfl_down_sync(0xffffffffu, v, o);
    if (lane == 0) warp_sum[wid] = v;
    __syncthreads();
    if (tid == 0) {
        float s = 0.f;
        #pragma unroll
        for (int i = 0; i < 8; i++) s += warp_sum[i];
        s_inv = 1.0f / s;
    }
    __syncthreads();
    float inv = s_inv;

    const float4* m4 = (const float4*)m_s;
    float4 mA = m4[lane];
    float4 mB = (lane < 17) ? m4[lane + 32] : make_float4(0.f, 0.f, 0.f, 0.f);

    int cbase = blockIdx.y * 256 + wid * 32;
    for (int it = 0; it < 32; it++) {
        int c = cbase + it;
        const float4* row = (const float4*)(feat + ((size_t)b * CH + c) * HW);
        float4 f = row[lane];
        float s = f.x * mA.x + f.y * mA.y + f.z * mA.z + f.w * mA.w;
        if (lane < 17) {
            float4 f2 = row[lane + 32];
            s += f2.x * mB.x + f2.y * mB.y + f2.z * mB.z + f2.w * mB.w;
        }
        #pragma unroll
        for (int o = 16; o > 0; o >>= 1) s += __shfl_down_sync(0xffffffffu, s, o);
        if (lane == 0) g_attended[b * CH + c] = s * inv;
    }
}

// ---------------------------------------------------------------------------
// Kernel 2: group batches by expert (stable), tiles of <=24, reset counter.
// ---------------------------------------------------------------------------
__global__ void group_kernel(const void* __restrict__ inst) {
    int tid = threadIdx.x;
    __shared__ int odd_nz;
    __shared__ int sh_e[BATCH];
    __shared__ int cnt[NEXP];
    __shared__ int off[NEXP + 1];

    if (tid == 0) { odd_nz = 0; g_ctr = 0; }
    __syncthreads();
    const int* iv = (const int*)inst;
    if (tid < BATCH / 2 && iv[2 * tid + 1] != 0) atomicExch(&odd_nz, 1);
    __syncthreads();

    int e;
    if (odd_nz == 0) e = (int)((const long long*)inst)[tid];
    else             e = iv[tid];

    sh_e[tid] = e;
    g_expert[tid] = e;
    if (tid < NEXP) cnt[tid] = 0;
    __syncthreads();

    atomicAdd(&cnt[e], 1);
    int rank = 0;
    for (int j = 0; j < tid; j++) rank += (sh_e[j] == e);
    __syncthreads();

    if (tid == 0) {
        off[0] = 0;
        for (int i = 0; i < NEXP; i++) off[i + 1] = off[i] + cnt[i];
        int nt = 0;
        for (int ei = 0; ei < NEXP; ei++)
            for (int s = 0; s < cnt[ei]; s += MT) {
                g_tile_e[nt]   = ei;
                g_tile_m0[nt]  = off[ei] + s;
                g_tile_cnt[nt] = min(MT, cnt[ei] - s);
                nt++;
            }
        g_numtiles = nt;
    }
    __syncthreads();
    g_perm[off[e] + rank] = tid;
}

// ---------------------------------------------------------------------------
// Kernel 3: stage quad-packed hi/lo B panels.
//   g_stage[tile][c][(sl*4+tig)*96 + 4n + {h0,h1,l0,l1}], k=c*32+sl*8+tig+4h.
// grid (16, MAXTILES) x 128 thr (4 chunks/block).
// ---------------------------------------------------------------------------
__global__ void stage_kernel() {
    int tile = blockIdx.y;
    if (tile >= g_numtiles) return;
    int k0 = blockIdx.x * 128;
    int tid = threadIdx.x;

    __shared__ float s[MT][128 + 4];
    __shared__ int s_bb[MT];
    if (tid < MT) {
        int m0 = g_tile_m0[tile], mcnt = g_tile_cnt[tile];
        s_bb[tid] = g_perm[m0 + min(tid, mcnt - 1)];
    }
    __syncthreads();

    #pragma unroll
    for (int i = 0; i < 6; i++) {
        int f4 = tid + 128 * i;
        int r = f4 >> 5, c = f4 & 31;
        float4 v = *(const float4*)(g_attended + (size_t)s_bb[r] * KDIM + k0 + c * 4);
        *(float4*)&s[r][c * 4] = v;
    }
    __syncthreads();

    int p = tid & 63, half = tid >> 6;
    int cc = p >> 4, sl = (p >> 2) & 3, tig = p & 3;
    int kl = cc * 32 + sl * 8 + tig;
    int c  = blockIdx.x * 4 + cc;
    float* dst = &g_stage[tile][c][(sl * 4 + tig) * BQROW];

    #pragma unroll
    for (int i = 0; i < 12; i++) {
        int n = half * 12 + i;
        float x0 = s[n][kl], x1 = s[n][kl + 4];
        float h0 = __uint_as_float(__float_as_uint(x0) & 0xFFFFE000u);
        float h1 = __uint_as_float(__float_as_uint(x1) & 0xFFFFE000u);
        *(float4*)(dst + 4 * n) = make_float4(h0, h1, x0 - h0, x1 - h1);
    }
}

// ---------------------------------------------------------------------------
// Kernel 4: persistent work-stealing grouped GEMM, mma.sync tf32 (3xTF32,
// truncation split: HW reads top-19 bits of the b32 operand).
// Item = (tile, ablock, kquarter): 16 chunks -> ~3384 items over 888 CTAs.
// ---------------------------------------------------------------------------
__global__ __launch_bounds__(128, 6)
void gemm_kernel(const float* __restrict__ W) {
    extern __shared__ __align__(16) float dsm[];
    uint32_t sm_u = (uint32_t)__cvta_generic_to_shared(dsm);

    int tid  = threadIdx.x;
    int w    = tid >> 5, lane = tid & 31;
    int g    = lane >> 2, tig = lane & 3;
    int r0 = tid >> 3, c4 = tid & 7;
    uint32_t adst0 = sm_u + (SM_A + r0 * AP + c4 * 4) * 4;
    int brow = tid / 24 * BQPITCH + (tid % 24) * 4;          // B copy dst (j=tid)

    __shared__ int s_bb[MT];
    __shared__ int s_item;

    int numtiles = g_numtiles;
    int total = numtiles * NABLK * NKQ;

    for (;;) {
        if (tid == 0) s_item = atomicAdd(&g_ctr, 1);
        __syncthreads();            // also: prior epilogue done before s_bb rewrite
        int it = s_item;
        if (it >= total) break;

        int kq   = it & (NKQ - 1);
        int r    = it >> 2;
        int tile = r % numtiles;
        int ab   = r / numtiles;
        int e    = g_tile_e[tile];
        int mcnt = g_tile_cnt[tile];
        int nf   = (mcnt + 7) >> 3;
        int a0   = ab * AB;

        if (tid < MT) s_bb[tid] = g_perm[g_tile_m0[tile] + min(tid, mcnt - 1)];
        __syncthreads();

        const char* Wexp = (const char*)(W + (size_t)e * NA * KDIM)
                         + (size_t)kq * (NCHQ * KC * 4);
        uint32_t a_off[4];
        #pragma unroll
        for (int j = 0; j < 4; j++)
            a_off[j] = (uint32_t)min(a0 + r0 + 16 * j, NA - 1) * (KDIM * 4) + c4 * 16;
        const char* bsrc = (const char*)&g_stage[tile][kq * NCHQ][0];

        auto issue = [&](int c) {
            int buf = c & 1;
            const char* wsrc = Wexp + (size_t)c * (KC * 4);
            uint32_t ad = adst0 + buf * (AB * AP * 4);
            #pragma unroll
            for (int j = 0; j < 4; j++)
                cp16(ad + j * (16 * AP * 4), wsrc + a_off[j]);
            // B: 384 f4 per buffer (16 rows x 24 quads), 3 per thread
            const char* bc = bsrc + (size_t)c * (16 * BQROW * 4);
            uint32_t bd = sm_u + (SM_B + buf * (16 * BQPITCH)) * 4;
            #pragma unroll
            for (int i = 0; i < 3; i++) {
                int j = tid + 128 * i;
                int rr = j / 24, cc_ = j % 24;
                cp16(bd + (rr * BQPITCH + cc_ * 4) * 4, bc + j * 16);
            }
        };

        issue(0); cp_commit();
        issue(1); cp_commit();

        float acc[3][4];
        #pragma unroll
        for (int f = 0; f < 3; f++)
            #pragma unroll
            for (int q = 0; q < 4; q++) acc[f][q] = 0.f;

        for (int c = 0; c < NCHQ; c++) {
            cp_wait1();
            __syncthreads();
            int buf = c & 1;
            const float* As = dsm + SM_A + buf * (AB * AP) + w * 16 * AP;
            const float* Bc = dsm + SM_B + buf * (16 * BQPITCH);

            #pragma unroll
            for (int sl = 0; sl < KC / 8; sl++) {
                int kk = sl * 8;
                float a0f = As[g * AP + kk + tig];
                float a1f = As[(g + 8) * AP + kk + tig];
                float a2f = As[g * AP + kk + tig + 4];
                float a3f = As[(g + 8) * AP + kk + tig + 4];
                uint32_t ahi[4], alo[4];
                ahi[0] = __float_as_uint(a0f) & 0xFFFFE000u;
                ahi[1] = __float_as_uint(a1f) & 0xFFFFE000u;
                ahi[2] = __float_as_uint(a2f) & 0xFFFFE000u;
                ahi[3] = __float_as_uint(a3f) & 0xFFFFE000u;
                alo[0] = __float_as_uint(a0f - __uint_as_float(ahi[0]));
                alo[1] = __float_as_uint(a1f - __uint_as_float(ahi[1]));
                alo[2] = __float_as_uint(a2f - __uint_as_float(ahi[2]));
                alo[3] = __float_as_uint(a3f - __uint_as_float(ahi[3]));

                const float* bp = Bc + (sl * 4 + tig) * BQPITCH + 4 * g;
                float4 bq[3];
                #pragma unroll
                for (int f = 0; f < 3; f++)
                    if (f < nf) bq[f] = *(const float4*)(bp + 32 * f);
                #pragma unroll
                for (int f = 0; f < 3; f++)
                    if (f < nf)
                        mma8(acc[f], ahi, __float_as_uint(bq[f].x),
                                          __float_as_uint(bq[f].y));
                #pragma unroll
                for (int f = 0; f < 3; f++)
                    if (f < nf)
                        mma8(acc[f], ahi, __float_as_uint(bq[f].z),
                                          __float_as_uint(bq[f].w));
                #pragma unroll
                for (int f = 0; f < 3; f++)
                    if (f < nf)
                        mma8(acc[f], alo, __float_as_uint(bq[f].x),
                                          __float_as_uint(bq[f].y));
            }
            __syncthreads();
            if (c + 2 < NCHQ) issue(c + 2);
            cp_commit();
        }

        // ---- epilogue: write K-quarter partials ----
        float* po = &g_partial[kq][0];
        int ra = a0 + w * 16 + g;
        int rb = ra + 8;
        #pragma unroll
        for (int f = 0; f < 3; f++) {
            int n0 = 8 * f + 2 * tig, n1 = n0 + 1;
            if (n0 < mcnt) {
                if (ra < NA) po[(size_t)s_bb[n0] * NA + ra] = acc[f][0];
                if (rb < NA) po[(size_t)s_bb[n0] * NA + rb] = acc[f][2];
            }
            if (n1 < mcnt) {
                if (ra < NA) po[(size_t)s_bb[n1] * NA + ra] = acc[f][1];
                if (rb < NA) po[(size_t)s_bb[n1] * NA + rb] = acc[f][3];
            }
        }
    }
}

// ---------------------------------------------------------------------------
// Kernel 5: out = sum_q partial[q] + bias[expert[b]]  (float4).
// ---------------------------------------------------------------------------
__global__ void reduce_kernel(const float* __restrict__ bias,
                              float* __restrict__ out) {
    int idx = blockIdx.x * 256 + threadIdx.x;       // 0..191999
    int b = idx / (NA / 4), q = idx % (NA / 4);
    int e = g_expert[b];
    size_t off = (size_t)b * NA + q * 4;
    float4 bv = *(const float4*)(bias + (size_t)e * NA + q * 4);
    float4 o = bv;
    #pragma unroll
    for (int h = 0; h < NKQ; h++) {
        float4 p = *(const float4*)(&g_partial[h][off]);
        o.x += p.x; o.y += p.y; o.z += p.z; o.w += p.w;
    }
    *(float4*)(out + off) = o;
}

// ---------------------------------------------------------------------------
extern "C" void kernel_launch(void* const* d_in, const int* in_sizes, int n_in,
                              void* d_out, int out_size) {
    const float* mask = (const float*)d_in[0];
    const float* feat = (const float*)d_in[1];
    const float* W    = (const float*)d_in[2];
    const float* bias = (const float*)d_in[3];
    const void*  inst = d_in[4];
    float* out = (float*)d_out;

    const int GEMM_SMEM = SM_TOT * 4;   // 31744 B
    cudaFuncSetAttribute(gemm_kernel,
                         cudaFuncAttributeMaxDynamicSharedMemorySize, GEMM_SMEM);

    pool_kernel<<<dim3(BATCH, 8), 256>>>(mask, feat);
    group_kernel<<<1, BATCH>>>(inst);
    stage_kernel<<<dim3(KDIM / 128, MAXTILES), 128>>>();
    gemm_kernel<<<GGRID, 128, GEMM_SMEM>>>(W);
    reduce_kernel<<<750, 256>>>(bias, out);
}

// round 12
// speedup vs baseline: 1.1265x; 1.0039x over previous
#include <cuda_runtime.h>
#include <cstdint>

#define BATCH 256
#define CH    2048
#define HW    196
#define NEXP  16
#define NA    3000
#define KDIM  2048

#define MT       24          // batches per expert tile (N)
#define MAXTILES 32
#define AB       64          // a-rows per item (M)
#define NABLK    47          // ceil(3000/64)
#define KC       32          // k-chunk (floats)
#define NCH      (KDIM/KC)   // 64 chunks total
#define NKQ      4           // K split into quarters
#define NCHQ     (NCH/NKQ)   // 16 chunks per item
#define AP       36          // A smem pitch (floats)
#define BQROW    96          // packed B row: 24 n x 4 (h0,h1,l0,l1)
#define BQPITCH  104         // smem pitch (floats): 8*tig+4*g banks, conflict-free
#define GGRID    888         // 148 SMs x 6 CTAs

// smem float offsets
#define SM_A   0                 // [2][64][36]   = 4608
#define SM_B   4608              // [2][16][104]  = 3328
#define SM_TOT 7936              // floats -> 31744 B

__device__ float g_attended[BATCH * CH];
__device__ int   g_perm[BATCH];
__device__ int   g_expert[BATCH];
__device__ int   g_tile_e[MAXTILES];
__device__ int   g_tile_m0[MAXTILES];
__device__ int   g_tile_cnt[MAXTILES];
__device__ int   g_numtiles;
__device__ int   g_ctr;
__device__ float g_partial[NKQ][BATCH * NA];                     // 12.3 MB
// staged B: [tile][chunk][row16][96]: row=(sl*4+tig), per n a float4 quad
__device__ __align__(16) float g_stage[MAXTILES][NCH][16 * BQROW];

// ---------------- helpers ----------------
__device__ __forceinline__ void mma8(float c[4], const uint32_t a[4],
                                     uint32_t b0, uint32_t b1) {
    asm volatile(
        "mma.sync.aligned.m16n8k8.row.col.f32.tf32.tf32.f32 "
        "{%0,%1,%2,%3}, {%4,%5,%6,%7}, {%8,%9}, {%0,%1,%2,%3};"
        : "+f"(c[0]), "+f"(c[1]), "+f"(c[2]), "+f"(c[3])
        : "r"(a[0]), "r"(a[1]), "r"(a[2]), "r"(a[3]), "r"(b0), "r"(b1));
}
__device__ __forceinline__ void cp16(uint32_t sdst, const void* g) {
    asm volatile("cp.async.cg.shared.global [%0], [%1], 16;" :: "r"(sdst), "l"(g));
}
__device__ __forceinline__ void cp_commit() {
    asm volatile("cp.async.commit_group;" ::: "memory");
}
__device__ __forceinline__ void cp_wait1() {
    asm volatile("cp.async.wait_group 1;" ::: "memory");
}

// ---------------------------------------------------------------------------
// Kernel 1: masked weighted average pool (DRAM-bound, at floor).
// ---------------------------------------------------------------------------
__global__ void pool_kernel(const float* __restrict__ mask,
                            const float* __restrict__ feat) {
    int b   = blockIdx.x;
    int tid = threadIdx.x;
    int wid = tid >> 5, lane = tid & 31;

    __shared__ __align__(16) float m_s[HW];
    __shared__ float warp_sum[8];
    __shared__ float s_inv;

    float v = 0.f;
    if (tid < HW) {
        v = mask[b * HW + tid] + 1e-10f;
        m_s[tid] = v;
    }
    #pragma unroll
    for (int o = 16; o > 0; o >>= 1) v += __shfl_down_sync(0xffffffffu, v, o);
    if (lane == 0) warp_sum[wid] = v;
    __syncthreads();
    if (tid == 0) {
        float s = 0.f;
        #pragma unroll
        for (int i = 0; i < 8; i++) s += warp_sum[i];
        s_inv = 1.0f / s;
    }
    __syncthreads();
    float inv = s_inv;

    const float4* m4 = (const float4*)m_s;
    float4 mA = m4[lane];
    float4 mB = (lane < 17) ? m4[lane + 32] : make_float4(0.f, 0.f, 0.f, 0.f);

    int cbase = blockIdx.y * 256 + wid * 32;
    for (int it = 0; it < 32; it++) {
        int c = cbase + it;
        const float4* row = (const float4*)(feat + ((size_t)b * CH + c) * HW);
        float4 f = row[lane];
        float s = f.x * mA.x + f.y * mA.y + f.z * mA.z + f.w * mA.w;
        if (lane < 17) {
            float4 f2 = row[lane + 32];
            s += f2.x * mB.x + f2.y * mB.y + f2.z * mB.z + f2.w * mB.w;
        }
        #pragma unroll
        for (int o = 16; o > 0; o >>= 1) s += __shfl_down_sync(0xffffffffu, s, o);
        if (lane == 0) g_attended[b * CH + c] = s * inv;
    }
}

// ---------------------------------------------------------------------------
// Kernel 2: group batches by expert (stable), tiles of <=24, reset counter.
// ---------------------------------------------------------------------------
__global__ void group_kernel(const void* __restrict__ inst) {
    int tid = threadIdx.x;
    __shared__ int odd_nz;
    __shared__ int sh_e[BATCH];
    __shared__ int cnt[NEXP];
    __shared__ int off[NEXP + 1];

    if (tid == 0) { odd_nz = 0; g_ctr = 0; }
    __syncthreads();
    const int* iv = (const int*)inst;
    if (tid < BATCH / 2 && iv[2 * tid + 1] != 0) atomicExch(&odd_nz, 1);
    __syncthreads();

    int e;
    if (odd_nz == 0) e = (int)((const long long*)inst)[tid];
    else             e = iv[tid];

    sh_e[tid] = e;
    g_expert[tid] = e;
    if (tid < NEXP) cnt[tid] = 0;
    __syncthreads();

    atomicAdd(&cnt[e], 1);
    int rank = 0;
    for (int j = 0; j < tid; j++) rank += (sh_e[j] == e);
    __syncthreads();

    if (tid == 0) {
        off[0] = 0;
        for (int i = 0; i < NEXP; i++) off[i + 1] = off[i] + cnt[i];
        int nt = 0;
        for (int ei = 0; ei < NEXP; ei++)
            for (int s = 0; s < cnt[ei]; s += MT) {
                g_tile_e[nt]   = ei;
                g_tile_m0[nt]  = off[ei] + s;
                g_tile_cnt[nt] = min(MT, cnt[ei] - s);
                nt++;
            }
        g_numtiles = nt;
    }
    __syncthreads();
    g_perm[off[e] + rank] = tid;
}

// ---------------------------------------------------------------------------
// Kernel 3: stage quad-packed hi/lo B panels.
//   g_stage[tile][c][(sl*4+tig)*96 + 4n + {h0,h1,l0,l1}], k=c*32+sl*8+tig+4h.
// grid (16, MAXTILES) x 128 thr (4 chunks/block).
// ---------------------------------------------------------------------------
__global__ void stage_kernel() {
    int tile = blockIdx.y;
    if (tile >= g_numtiles) return;
    int k0 = blockIdx.x * 128;
    int tid = threadIdx.x;

    __shared__ float s[MT][128 + 4];
    __shared__ int s_bb[MT];
    if (tid < MT) {
        int m0 = g_tile_m0[tile], mcnt = g_tile_cnt[tile];
        s_bb[tid] = g_perm[m0 + min(tid, mcnt - 1)];
    }
    __syncthreads();

    #pragma unroll
    for (int i = 0; i < 6; i++) {
        int f4 = tid + 128 * i;
        int r = f4 >> 5, c = f4 & 31;
        float4 v = *(const float4*)(g_attended + (size_t)s_bb[r] * KDIM + k0 + c * 4);
        *(float4*)&s[r][c * 4] = v;
    }
    __syncthreads();

    int p = tid & 63, half = tid >> 6;
    int cc = p >> 4, sl = (p >> 2) & 3, tig = p & 3;
    int kl = cc * 32 + sl * 8 + tig;
    int c  = blockIdx.x * 4 + cc;
    float* dst = &g_stage[tile][c][(sl * 4 + tig) * BQROW];

    #pragma unroll
    for (int i = 0; i < 12; i++) {
        int n = half * 12 + i;
        float x0 = s[n][kl], x1 = s[n][kl + 4];
        float h0 = __uint_as_float(__float_as_uint(x0) & 0xFFFFE000u);
        float h1 = __uint_as_float(__float_as_uint(x1) & 0xFFFFE000u);
        *(float4*)(dst + 4 * n) = make_float4(h0, h1, x0 - h0, x1 - h1);
    }
}

// ---------------------------------------------------------------------------
// Kernel 4: persistent work-stealing grouped GEMM, mma.sync tf32 (3xTF32,
// truncation split: HW reads top-19 bits of the b32 operand).
// Item = (tile, ablock, kquarter): 16 chunks -> ~3384 items over 888 CTAs.
// ---------------------------------------------------------------------------
__global__ __launch_bounds__(128, 6)
void gemm_kernel(const float* __restrict__ W) {
    extern __shared__ __align__(16) float dsm[];
    uint32_t sm_u = (uint32_t)__cvta_generic_to_shared(dsm);

    int tid  = threadIdx.x;
    int w    = tid >> 5, lane = tid & 31;
    int g    = lane >> 2, tig = lane & 3;
    int r0 = tid >> 3, c4 = tid & 7;
    uint32_t adst0 = sm_u + (SM_A + r0 * AP + c4 * 4) * 4;
    int brow = tid / 24 * BQPITCH + (tid % 24) * 4;          // B copy dst (j=tid)

    __shared__ int s_bb[MT];
    __shared__ int s_item;

    int numtiles = g_numtiles;
    int total = numtiles * NABLK * NKQ;

    for (;;) {
        if (tid == 0) s_item = atomicAdd(&g_ctr, 1);
        __syncthreads();            // also: prior epilogue done before s_bb rewrite
        int it = s_item;
        if (it >= total) break;

        int kq   = it & (NKQ - 1);
        int r    = it >> 2;
        int tile = r % numtiles;
        int ab   = r / numtiles;
        int e    = g_tile_e[tile];
        int mcnt = g_tile_cnt[tile];
        int nf   = (mcnt + 7) >> 3;
        int a0   = ab * AB;

        if (tid < MT) s_bb[tid] = g_perm[g_tile_m0[tile] + min(tid, mcnt - 1)];
        __syncthreads();

        const char* Wexp = (const char*)(W + (size_t)e * NA * KDIM)
                         + (size_t)kq * (NCHQ * KC * 4);
        uint32_t a_off[4];
        #pragma unroll
        for (int j = 0; j < 4; j++)
            a_off[j] = (uint32_t)min(a0 + r0 + 16 * j, NA - 1) * (KDIM * 4) + c4 * 16;
        const char* bsrc = (const char*)&g_stage[tile][kq * NCHQ][0];

        auto issue = [&](int c) {
            int buf = c & 1;
            const char* wsrc = Wexp + (size_t)c * (KC * 4);
            uint32_t ad = adst0 + buf * (AB * AP * 4);
            #pragma unroll
            for (int j = 0; j < 4; j++)
                cp16(ad + j * (16 * AP * 4), wsrc + a_off[j]);
            // B: 384 f4 per buffer (16 rows x 24 quads), 3 per thread
            const char* bc = bsrc + (size_t)c * (16 * BQROW * 4);
            uint32_t bd = sm_u + (SM_B + buf * (16 * BQPITCH)) * 4;
            #pragma unroll
            for (int i = 0; i < 3; i++) {
                int j = tid + 128 * i;
                int rr = j / 24, cc_ = j % 24;
                cp16(bd + (rr * BQPITCH + cc_ * 4) * 4, bc + j * 16);
            }
        };

        issue(0); cp_commit();
        issue(1); cp_commit();

        float acc[3][4];
        #pragma unroll
        for (int f = 0; f < 3; f++)
            #pragma unroll
            for (int q = 0; q < 4; q++) acc[f][q] = 0.f;

        for (int c = 0; c < NCHQ; c++) {
            cp_wait1();
            __syncthreads();
            int buf = c & 1;
            const float* As = dsm + SM_A + buf * (AB * AP) + w * 16 * AP;
            const float* Bc = dsm + SM_B + buf * (16 * BQPITCH);

            #pragma unroll
            for (int sl = 0; sl < KC / 8; sl++) {
                int kk = sl * 8;
                float a0f = As[g * AP + kk + tig];
                float a1f = As[(g + 8) * AP + kk + tig];
                float a2f = As[g * AP + kk + tig + 4];
                float a3f = As[(g + 8) * AP + kk + tig + 4];
                uint32_t ahi[4], alo[4];
                ahi[0] = __float_as_uint(a0f) & 0xFFFFE000u;
                ahi[1] = __float_as_uint(a1f) & 0xFFFFE000u;
                ahi[2] = __float_as_uint(a2f) & 0xFFFFE000u;
                ahi[3] = __float_as_uint(a3f) & 0xFFFFE000u;
                alo[0] = __float_as_uint(a0f - __uint_as_float(ahi[0]));
                alo[1] = __float_as_uint(a1f - __uint_as_float(ahi[1]));
                alo[2] = __float_as_uint(a2f - __uint_as_float(ahi[2]));
                alo[3] = __float_as_uint(a3f - __uint_as_float(ahi[3]));

                const float* bp = Bc + (sl * 4 + tig) * BQPITCH + 4 * g;
                float4 bq[3];
                #pragma unroll
                for (int f = 0; f < 3; f++)
                    if (f < nf) bq[f] = *(const float4*)(bp + 32 * f);
                #pragma unroll
                for (int f = 0; f < 3; f++)
                    if (f < nf)
                        mma8(acc[f], ahi, __float_as_uint(bq[f].x),
                                          __float_as_uint(bq[f].y));
                #pragma unroll
                for (int f = 0; f < 3; f++)
                    if (f < nf)
                        mma8(acc[f], ahi, __float_as_uint(bq[f].z),
                                          __float_as_uint(bq[f].w));
                #pragma unroll
                for (int f = 0; f < 3; f++)
                    if (f < nf)
                        mma8(acc[f], alo, __float_as_uint(bq[f].x),
                                          __float_as_uint(bq[f].y));
            }
            __syncthreads();
            if (c + 2 < NCHQ) issue(c + 2);
            cp_commit();
        }

        // ---- epilogue: write K-quarter partials ----
        float* po = &g_partial[kq][0];
        int ra = a0 + w * 16 + g;
        int rb = ra + 8;
        #pragma unroll
        for (int f = 0; f < 3; f++) {
            int n0 = 8 * f + 2 * tig, n1 = n0 + 1;
            if (n0 < mcnt) {
                if (ra < NA) po[(size_t)s_bb[n0] * NA + ra] = acc[f][0];
                if (rb < NA) po[(size_t)s_bb[n0] * NA + rb] = acc[f][2];
            }
            if (n1 < mcnt) {
                if (ra < NA) po[(size_t)s_bb[n1] * NA + ra] = acc[f][1];
                if (rb < NA) po[(size_t)s_bb[n1] * NA + rb] = acc[f][3];
            }
        }
    }
}

// ---------------------------------------------------------------------------
// Kernel 5: out = sum_q partial[q] + bias[expert[b]]  (float4).
// ---------------------------------------------------------------------------
__global__ void reduce_kernel(const float* __restrict__ bias,
                              float* __restrict__ out) {
    int idx = blockIdx.x * 256 + threadIdx.x;       // 0..191999
    int b = idx / (NA / 4), q = idx % (NA / 4);
    int e = g_expert[b];
    size_t off = (size_t)b * NA + q * 4;
    float4 bv = *(const float4*)(bias + (size_t)e * NA + q * 4);
    float4 o = bv;
    #pragma unroll
    for (int h = 0; h < NKQ; h++) {
        float4 p = *(const float4*)(&g_partial[h][off]);
        o.x += p.x; o.y += p.y; o.z += p.z; o.w += p.w;
    }
    *(float4*)(out + off) = o;
}

// ---------------------------------------------------------------------------
extern "C" void kernel_launch(void* const* d_in, const int* in_sizes, int n_in,
                              void* d_out, int out_size) {
    const float* mask = (const float*)d_in[0];
    const float* feat = (const float*)d_in[1];
    const float* W    = (const float*)d_in[2];
    const float* bias = (const float*)d_in[3];
    const void*  inst = d_in[4];
    float* out = (float*)d_out;

    const int GEMM_SMEM = SM_TOT * 4;   // 31744 B
    cudaFuncSetAttribute(gemm_kernel,
                         cudaFuncAttributeMaxDynamicSharedMemorySize, GEMM_SMEM);

    pool_kernel<<<dim3(BATCH, 8), 256>>>(mask, feat);
    group_kernel<<<1, BATCH>>>(inst);
    stage_kernel<<<dim3(KDIM / 128, MAXTILES), 128>>>();
    gemm_kernel<<<GGRID, 128, GEMM_SMEM>>>(W);
    reduce_kernel<<<750, 256>>>(bias, out);
}